// round 10
// baseline (speedup 1.0000x reference)
#include <cuda_runtime.h>
#include <cuda_bf16.h>
#include <math.h>
#include <stdint.h>

#define Bn 4
#define Cn 512
#define Ln 4096
#define CKn 64
#define CGn 256

// Scratch (allocation-free rule: static __device__ arrays)
__device__ __nv_bfloat16 g_th_hi[Bn * Ln * CKn];   // theta pre-scaled by log2(e)
__device__ __nv_bfloat16 g_th_lo[Bn * Ln * CKn];
__device__ __nv_bfloat16 g_ph_hi[Bn * Ln * CKn];
__device__ __nv_bfloat16 g_ph_lo[Bn * Ln * CKn];
__device__ float g_gv[Bn * Ln * CGn];
__device__ __nv_bfloat16 g_gt_hi[Bn * CGn * Ln];
__device__ __nv_bfloat16 g_gt_lo[Bn * CGn * Ln];
__device__ float g_colinv[Bn * Ln];
__device__ __nv_bfloat16 g_P_hi[(size_t)Bn * Ln * Ln];  // unnormalized exp2(S')
__device__ __nv_bfloat16 g_P_lo[(size_t)Bn * Ln * Ln];
__device__ __nv_bfloat16 g_ag_hi[Bn * Ln * CGn];
__device__ __nv_bfloat16 g_ag_lo[Bn * Ln * CGn];

__device__ __forceinline__ uint32_t smem_u32(const void* p) {
    uint32_t a;
    asm("{ .reg .u64 t; cvta.to.shared.u64 t, %1; cvt.u32.u64 %0, t; }" : "=r"(a) : "l"(p));
    return a;
}

#define LDSM_X4(r0, r1, r2, r3, addr) \
    asm volatile("ldmatrix.sync.aligned.m8n8.x4.shared.b16 {%0,%1,%2,%3}, [%4];" \
                 : "=r"(r0), "=r"(r1), "=r"(r2), "=r"(r3) : "r"(addr))

#define LDSM_X4_T(r0, r1, r2, r3, addr) \
    asm volatile("ldmatrix.sync.aligned.m8n8.x4.trans.shared.b16 {%0,%1,%2,%3}, [%4];" \
                 : "=r"(r0), "=r"(r1), "=r"(r2), "=r"(r3) : "r"(addr))

#define MMA_BF16(d, a, b0, b1) \
    asm volatile("mma.sync.aligned.m16n8k16.row.col.f32.bf16.bf16.f32 " \
                 "{%0,%1,%2,%3},{%4,%5,%6,%7},{%8,%9},{%0,%1,%2,%3};" \
                 : "+f"((d)[0]), "+f"((d)[1]), "+f"((d)[2]), "+f"((d)[3]) \
                 : "r"((a)[0]), "r"((a)[1]), "r"((a)[2]), "r"((a)[3]), "r"(b0), "r"(b1))

#define CP_ASYNC16(smem, gptr) \
    asm volatile("cp.async.cg.shared.global [%0], [%1], 16;" :: "r"(smem), "l"(gptr))
#define CP_COMMIT() asm volatile("cp.async.commit_group;")
#define CP_WAIT0()  asm volatile("cp.async.wait_group 0;")
#define CP_WAIT1()  asm volatile("cp.async.wait_group 1;")
#define CP_WAIT2()  asm volatile("cp.async.wait_group 2;")

__device__ __forceinline__ void split_bf16(float f, __nv_bfloat16& hi, __nv_bfloat16& lo) {
    hi = __float2bfloat16(f);
    lo = __float2bfloat16(f - __bfloat162float(hi));
}
__device__ __forceinline__ uint32_t packbf(__nv_bfloat16 a, __nv_bfloat16 b) {
    return ((uint32_t)__bfloat16_as_ushort(b) << 16) | __bfloat16_as_ushort(a);
}
__device__ __forceinline__ float ex2f(float x) {
    float r;
    asm("ex2.approx.f32 %0, %1;" : "=f"(r) : "f"(x));
    return r;
}

// ===========================================================================
// K1: projections via bf16x3 mma. theta scaled by log2(e) (ex2 softmax).
// ===========================================================================
#define P_SMEM 131072

__global__ void __launch_bounds__(256, 1) proj_mma(const float* __restrict__ x,
                            const float* __restrict__ Wt, const float* __restrict__ bt,
                            const float* __restrict__ Wp, const float* __restrict__ bp,
                            const float* __restrict__ Wg, const float* __restrict__ bg) {
    extern __shared__ char sm[];
    uint32_t sb = smem_u32(sm);
    int tid = threadIdx.x, lane = tid & 31, wid = tid >> 5;
    int warp_m = wid & 3, warp_n = wid >> 2;
    int l0 = blockIdx.x * 128, grp = blockIdx.y, b = blockIdx.z;
    const float* xb = x + (size_t)b * Cn * Ln;

    float4 rx[8], rw[8];
#pragma unroll
    for (int t = 0; t < 8; t++) {
        int idx = tid + t * 256, r = idx >> 5, q = idx & 31;
        rx[t] = *(const float4*)&xb[(size_t)r * Ln + l0 + q * 4];
    }
#pragma unroll
    for (int t = 0; t < 8; t++) {
        int idx = tid + t * 256, r = idx >> 4, q = idx & 15;
        const float* Wrow;
        if (grp == 0) Wrow = (r < 64) ? Wt + (size_t)r * Cn : Wp + (size_t)(r - 64) * Cn;
        else          Wrow = Wg + (size_t)((grp - 1) * 128 + r) * Cn;
        rw[t] = *(const float4*)&Wrow[q * 4];
    }

    float acc[2][8][4];
#pragma unroll
    for (int mt = 0; mt < 2; mt++)
#pragma unroll
        for (int nt = 0; nt < 8; nt++)
#pragma unroll
            for (int j = 0; j < 4; j++) acc[mt][nt][j] = 0.f;

    int b_row_off = (lane >> 4) * 8 + (lane & 7);
    int b_half = ((lane >> 3) & 1) * 16;
    uint32_t swl = (uint32_t)(lane & 7) << 4;

    for (int kc = 0; kc < 8; kc++) {
        uint32_t xa = sb + (uint32_t)(kc & 1) * 32768;
        uint32_t wb = sb + 65536 + (uint32_t)(kc & 1) * 32768;
#pragma unroll
        for (int t = 0; t < 8; t++) {
            int idx = tid + t * 256, r = idx >> 5, q = idx & 31;
            __nv_bfloat16 h0, e0, h1, e1, h2, e2, h3, e3;
            split_bf16(rx[t].x, h0, e0); split_bf16(rx[t].y, h1, e1);
            split_bf16(rx[t].z, h2, e2); split_bf16(rx[t].w, h3, e3);
            uint32_t so = r * 256 + ((q * 8) ^ ((r & 7) << 4));
            *(uint2*)(sm + (xa - sb) + so) = make_uint2(packbf(h0, h1), packbf(h2, h3));
            *(uint2*)(sm + (xa - sb) + 16384 + so) = make_uint2(packbf(e0, e1), packbf(e2, e3));
        }
#pragma unroll
        for (int t = 0; t < 8; t++) {
            int idx = tid + t * 256, r = idx >> 4, q = idx & 15;
            __nv_bfloat16 h0, e0, h1, e1, h2, e2, h3, e3;
            split_bf16(rw[t].x, h0, e0); split_bf16(rw[t].y, h1, e1);
            split_bf16(rw[t].z, h2, e2); split_bf16(rw[t].w, h3, e3);
            uint32_t so = r * 128 + ((q * 8) ^ ((r & 7) << 4));
            *(uint2*)(sm + (wb - sb) + so) = make_uint2(packbf(h0, h1), packbf(h2, h3));
            *(uint2*)(sm + (wb - sb) + 16384 + so) = make_uint2(packbf(e0, e1), packbf(e2, e3));
        }
        __syncthreads();
        if (kc < 7) {
            int k0n = (kc + 1) * 64;
#pragma unroll
            for (int t = 0; t < 8; t++) {
                int idx = tid + t * 256, r = idx >> 5, q = idx & 31;
                rx[t] = *(const float4*)&xb[(size_t)(k0n + r) * Ln + l0 + q * 4];
            }
#pragma unroll
            for (int t = 0; t < 8; t++) {
                int idx = tid + t * 256, r = idx >> 4, q = idx & 15;
                const float* Wrow;
                if (grp == 0) Wrow = (r < 64) ? Wt + (size_t)r * Cn : Wp + (size_t)(r - 64) * Cn;
                else          Wrow = Wg + (size_t)((grp - 1) * 128 + r) * Cn;
                rw[t] = *(const float4*)&Wrow[k0n + q * 4];
            }
        }
#pragma unroll
        for (int ks = 0; ks < 4; ks++) {
            uint32_t ah[2][4], al[2][4], bh[4][4], bl[4][4];
            uint32_t srow = (uint32_t)(ks * 16 + (lane & 7) + ((lane >> 4) & 1) * 8);
#pragma unroll
            for (int mt = 0; mt < 2; mt++) {
                uint32_t mb = (uint32_t)(warp_m * 32 + mt * 16 + ((lane >> 3) & 1) * 8) * 2;
                uint32_t ad = xa + srow * 256 + (mb ^ swl);
                LDSM_X4_T(ah[mt][0], ah[mt][1], ah[mt][2], ah[mt][3], ad);
                LDSM_X4_T(al[mt][0], al[mt][1], al[mt][2], al[mt][3], ad + 16384);
            }
#pragma unroll
            for (int np = 0; np < 4; np++) {
                uint32_t row = (uint32_t)(warp_n * 64 + np * 16 + b_row_off);
                uint32_t ad = wb + row * 128 + (((uint32_t)(ks * 32 + b_half)) ^ swl);
                LDSM_X4(bh[np][0], bh[np][1], bh[np][2], bh[np][3], ad);
                LDSM_X4(bl[np][0], bl[np][1], bl[np][2], bl[np][3], ad + 16384);
            }
#pragma unroll
            for (int mt = 0; mt < 2; mt++)
#pragma unroll
                for (int np = 0; np < 4; np++) {
                    MMA_BF16(acc[mt][2 * np],     ah[mt], bh[np][0], bh[np][1]);
                    MMA_BF16(acc[mt][2 * np],     ah[mt], bl[np][0], bl[np][1]);
                    MMA_BF16(acc[mt][2 * np],     al[mt], bh[np][0], bh[np][1]);
                    MMA_BF16(acc[mt][2 * np + 1], ah[mt], bh[np][2], bh[np][3]);
                    MMA_BF16(acc[mt][2 * np + 1], ah[mt], bl[np][2], bl[np][3]);
                    MMA_BF16(acc[mt][2 * np + 1], al[mt], bh[np][2], bh[np][3]);
                }
        }
        __syncthreads();
    }

    if (grp == 0) {
        __nv_bfloat16* ohi = (warp_n == 0 ? g_th_hi : g_ph_hi) + (size_t)b * Ln * CKn;
        __nv_bfloat16* olo = (warp_n == 0 ? g_th_lo : g_ph_lo) + (size_t)b * Ln * CKn;
        const float* bias = (warp_n == 0 ? bt : bp);
        float sc = (warp_n == 0) ? 1.4426950408889634f : 1.0f;  // log2(e) for theta
#pragma unroll
        for (int mt = 0; mt < 2; mt++)
#pragma unroll
            for (int nt = 0; nt < 8; nt++) {
                int r = warp_m * 32 + mt * 16 + (lane >> 2);
                int cl = nt * 8 + 2 * (lane & 3);
                float bv0 = bias[cl], bv1 = bias[cl + 1];
                float v00 = tanhf(acc[mt][nt][0] + bv0) * sc;
                float v01 = tanhf(acc[mt][nt][1] + bv1) * sc;
                float v10 = tanhf(acc[mt][nt][2] + bv0) * sc;
                float v11 = tanhf(acc[mt][nt][3] + bv1) * sc;
                __nv_bfloat16 h0, e0, h1, e1;
                split_bf16(v00, h0, e0); split_bf16(v01, h1, e1);
                size_t o = (size_t)(l0 + r) * CKn + cl;
                *(uint32_t*)((char*)ohi + o * 2) = packbf(h0, h1);
                *(uint32_t*)((char*)olo + o * 2) = packbf(e0, e1);
                split_bf16(v10, h0, e0); split_bf16(v11, h1, e1);
                o = (size_t)(l0 + r + 8) * CKn + cl;
                *(uint32_t*)((char*)ohi + o * 2) = packbf(h0, h1);
                *(uint32_t*)((char*)olo + o * 2) = packbf(e0, e1);
            }
    } else {
        float* outp = g_gv + (size_t)b * Ln * CGn;
        int goff = (grp - 1) * 128 + warp_n * 64;
#pragma unroll
        for (int mt = 0; mt < 2; mt++)
#pragma unroll
            for (int nt = 0; nt < 8; nt++) {
                int r = warp_m * 32 + mt * 16 + (lane >> 2);
                int cl = nt * 8 + 2 * (lane & 3);
                int c = goff + cl;
                float bv0 = bg[c], bv1 = bg[c + 1];
                float2 v0 = make_float2(acc[mt][nt][0] + bv0, acc[mt][nt][1] + bv1);
                float2 v1 = make_float2(acc[mt][nt][2] + bv0, acc[mt][nt][3] + bv1);
                *(float2*)&outp[(size_t)(l0 + r) * CGn + c] = v0;
                *(float2*)&outp[(size_t)(l0 + r + 8) * CGn + c] = v1;
            }
    }
}

// ===========================================================================
// K2: softstats — computes S once, emits P = exp2(S') (bf16 hi/lo, 268 MB)
// and per-column sums. 4-deep theta ring: one sync per chunk.
// ===========================================================================
#define S_PH 0
#define S_TH(s) (32768 + (s) * 32768)
#define S_WSM   163840
#define S_SMEM  165888

__global__ void __launch_bounds__(256, 1) softstats_kernel() {
    extern __shared__ char sm[];
    uint32_t sb = smem_u32(sm);
    int tid = threadIdx.x;
    int lane = tid & 31, wid = tid >> 5;
    int warp_m = wid & 3, warp_n = wid >> 2;
    int m0 = blockIdx.x * 128, b = blockIdx.y;

    const __nv_bfloat16* thh = g_th_hi + (size_t)b * Ln * CKn;
    const __nv_bfloat16* thl = g_th_lo + (size_t)b * Ln * CKn;
    const __nv_bfloat16* phh = g_ph_hi + (size_t)b * Ln * CKn;
    const __nv_bfloat16* phl = g_ph_lo + (size_t)b * Ln * CKn;

#pragma unroll
    for (int s = 0; s < 3; s++) {
#pragma unroll
        for (int t = 0; t < 4; t++) {
            int idx = tid + t * 256;
            int r = idx >> 3, q = idx & 7;
            uint32_t so = r * 128 + ((q * 16) ^ ((r & 7) << 4));
            CP_ASYNC16(sb + S_TH(s) + so, thh + ((size_t)(s * 128 + r)) * CKn + q * 8);
            CP_ASYNC16(sb + S_TH(s) + 16384 + so, thl + ((size_t)(s * 128 + r)) * CKn + q * 8);
        }
        CP_COMMIT();
    }
#pragma unroll
    for (int t = 0; t < 4; t++) {
        int idx = tid + t * 256;
        int r = idx >> 3, q = idx & 7;
        uint32_t so = r * 128 + ((q * 16) ^ ((r & 7) << 4));
        *(uint4*)(sm + S_PH + so) = *(const uint4*)(phh + ((size_t)(m0 + r)) * CKn + q * 8);
        *(uint4*)(sm + S_PH + 16384 + so) = *(const uint4*)(phl + ((size_t)(m0 + r)) * CKn + q * 8);
    }

    float sum[16];
#pragma unroll
    for (int i = 0; i < 16; i++) sum[i] = 0.f;

    int a_row_off = ((lane >> 3) & 1) * 8 + (lane & 7);
    int a_half = (lane >> 4) * 16;
    int b_row_off = (lane >> 4) * 8 + (lane & 7);
    int b_half = ((lane >> 3) & 1) * 16;
    uint32_t swl = (uint32_t)(lane & 7) << 4;

    for (int lc = 0; lc < 32; lc++) {
        CP_WAIT2();
        __syncthreads();
        {
            int ln = (lc + 3) & 31;
            uint32_t bufo = S_TH((lc + 3) & 3);
#pragma unroll
            for (int t = 0; t < 4; t++) {
                int idx = tid + t * 256;
                int r = idx >> 3, q = idx & 7;
                uint32_t so = r * 128 + ((q * 16) ^ ((r & 7) << 4));
                CP_ASYNC16(sb + bufo + so, thh + ((size_t)(ln * 128 + r)) * CKn + q * 8);
                CP_ASYNC16(sb + bufo + 16384 + so, thl + ((size_t)(ln * 128 + r)) * CKn + q * 8);
            }
            CP_COMMIT();
        }
        uint32_t thb = sb + S_TH(lc & 3);
        float acc[2][8][4];
#pragma unroll
        for (int mt = 0; mt < 2; mt++)
#pragma unroll
            for (int nt = 0; nt < 8; nt++)
#pragma unroll
                for (int j = 0; j < 4; j++) acc[mt][nt][j] = 0.f;

#pragma unroll
        for (int ks = 0; ks < 4; ks++) {
            int koff = ks * 32;
            uint32_t ah[2][4], al[2][4], bh[4][4], bl[4][4];
#pragma unroll
            for (int mt = 0; mt < 2; mt++) {
                uint32_t row = warp_m * 32 + mt * 16 + a_row_off;
                uint32_t ad = thb + row * 128 + (((uint32_t)(koff + a_half)) ^ swl);
                LDSM_X4(ah[mt][0], ah[mt][1], ah[mt][2], ah[mt][3], ad);
                LDSM_X4(al[mt][0], al[mt][1], al[mt][2], al[mt][3], ad + 16384);
            }
#pragma unroll
            for (int np = 0; np < 4; np++) {
                uint32_t row = warp_n * 64 + np * 16 + b_row_off;
                uint32_t ad = sb + S_PH + row * 128 + (((uint32_t)(koff + b_half)) ^ swl);
                LDSM_X4(bh[np][0], bh[np][1], bh[np][2], bh[np][3], ad);
                LDSM_X4(bl[np][0], bl[np][1], bl[np][2], bl[np][3], ad + 16384);
            }
#pragma unroll
            for (int mt = 0; mt < 2; mt++)
#pragma unroll
                for (int np = 0; np < 4; np++) {
                    MMA_BF16(acc[mt][2 * np],     ah[mt], bh[np][0], bh[np][1]);
                    MMA_BF16(acc[mt][2 * np],     ah[mt], bl[np][0], bl[np][1]);
                    MMA_BF16(acc[mt][2 * np],     al[mt], bh[np][0], bh[np][1]);
                    MMA_BF16(acc[mt][2 * np + 1], ah[mt], bh[np][2], bh[np][3]);
                    MMA_BF16(acc[mt][2 * np + 1], ah[mt], bl[np][2], bl[np][3]);
                    MMA_BF16(acc[mt][2 * np + 1], al[mt], bh[np][2], bh[np][3]);
                }
        }
        // exp2 -> column sums + P store (bf16 hi/lo)
#pragma unroll
        for (int mt = 0; mt < 2; mt++)
#pragma unroll
            for (int nt = 0; nt < 8; nt++) {
                float e0 = ex2f(acc[mt][nt][0]);
                float e1 = ex2f(acc[mt][nt][1]);
                float e2 = ex2f(acc[mt][nt][2]);
                float e3 = ex2f(acc[mt][nt][3]);
                sum[nt * 2]     += e0 + e2;
                sum[nt * 2 + 1] += e1 + e3;
                int lrow = lc * 128 + warp_m * 32 + mt * 16 + (lane >> 2);
                int mcol = m0 + warp_n * 64 + nt * 8 + 2 * (lane & 3);
                size_t o = ((size_t)b * Ln + lrow) * Ln + mcol;
                __nv_bfloat16 h0, l0_, h1, l1;
                split_bf16(e0, h0, l0_); split_bf16(e1, h1, l1);
                *(uint32_t*)((char*)g_P_hi + o * 2) = packbf(h0, h1);
                *(uint32_t*)((char*)g_P_lo + o * 2) = packbf(l0_, l1);
                o += (size_t)8 * Ln;
                split_bf16(e2, h0, l0_); split_bf16(e3, h1, l1);
                *(uint32_t*)((char*)g_P_hi + o * 2) = packbf(h0, h1);
                *(uint32_t*)((char*)g_P_lo + o * 2) = packbf(l0_, l1);
            }
    }

#pragma unroll
    for (int s = 4; s <= 16; s <<= 1)
#pragma unroll
        for (int i = 0; i < 16; i++)
            sum[i] += __shfl_xor_sync(0xffffffffu, sum[i], s);

    float* wsm = (float*)(sm + S_WSM);
    __syncthreads();
    if (lane < 4) {
#pragma unroll
        for (int nt = 0; nt < 8; nt++)
#pragma unroll
            for (int j = 0; j < 2; j++) {
                int c = warp_n * 64 + nt * 8 + 2 * lane + j;
                wsm[warp_m * 128 + c] = sum[nt * 2 + j];
            }
    }
    __syncthreads();
    if (tid < 128) {
        float S = 0.f;
#pragma unroll
        for (int w = 0; w < 4; w++) S += wsm[w * 128 + tid];
        g_colinv[b * Ln + m0 + tid] = 1.0f / S;
    }
}

// ===========================================================================
// K3: gT transpose+scale (unchanged).
// ===========================================================================
__global__ void transpose_scale_kernel() {
    __shared__ float t[32][33];
    int m0 = blockIdx.x * 32, c0 = blockIdx.y * 32, b = blockIdx.z;
    int tx = threadIdx.x, ty = threadIdx.y;
#pragma unroll
    for (int i = 0; i < 32; i += 8) {
        int m = m0 + ty + i;
        t[ty + i][tx] = g_gv[((size_t)b * Ln + m) * CGn + c0 + tx] * g_colinv[b * Ln + m];
    }
    __syncthreads();
#pragma unroll
    for (int i = 0; i < 32; i += 8) {
        float v = t[tx][ty + i];
        __nv_bfloat16 hi, lo;
        split_bf16(v, hi, lo);
        size_t o = ((size_t)b * CGn + c0 + ty + i) * Ln + m0 + tx;
        g_gt_hi[o] = hi;
        g_gt_lo[o] = lo;
    }
}

// ===========================================================================
// K4: attention GEMM2 only: AG = P @ gT^T, P streamed from gmem (cp.async).
// CTA 64l x 256c, warp_n splits m (K). P double-buffered, gT 4-quarter ring.
// SMEM: P stage s at s*32768 (hi/lo 16K); GT quarter q at 65536+q*32768.
// Total 196608. Grid (Ln/64, Bn).
// ===========================================================================
#define AT_P(s)   ((s) * 32768)
#define AT_GTQ(q) (65536 + (q) * 32768)
#define AT_RED    0
#define AT_SMEM   196608

__global__ void __launch_bounds__(256, 1) attn_fused() {
    extern __shared__ char sm[];
    uint32_t sb = smem_u32(sm);
    int tid = threadIdx.x;
    int lane = tid & 31, wid = tid >> 5;
    int warp_m = wid & 3, warp_n = wid >> 2;
    int l0 = blockIdx.x * 64, b = blockIdx.y;

    const __nv_bfloat16* Gh = g_gt_hi + (size_t)b * CGn * Ln;
    const __nv_bfloat16* Gl = g_gt_lo + (size_t)b * CGn * Ln;

#define REFILL_Q(Q) do { \
        int _kq = ((Q) >> 2) & 31, _cq = (Q) & 3; \
        uint32_t _bo = AT_GTQ(_cq); \
        _Pragma("unroll") \
        for (int _t = 0; _t < 4; _t++) { \
            int _idx = tid + _t * 256, _r = _idx >> 4, _q = _idx & 15; \
            uint32_t _so = _r * 256 + ((_q * 16) ^ ((_r & 7) << 4)); \
            CP_ASYNC16(sb + _bo + _so, Gh + (size_t)(_cq * 64 + _r) * Ln + _kq * 128 + _q * 8); \
            CP_ASYNC16(sb + _bo + 16384 + _so, Gl + (size_t)(_cq * 64 + _r) * Ln + _kq * 128 + _q * 8); \
        } \
    } while (0)
#define REFILL_P(K) do { \
        int _k = (K) & 31, _s = (K) & 1; \
        _Pragma("unroll") \
        for (int _t = 0; _t < 4; _t++) { \
            int _idx = tid + _t * 256, _r = _idx >> 4, _q = _idx & 15; \
            uint32_t _so = _r * 256 + ((_q * 16) ^ ((_r & 7) << 4)); \
            size_t _go = ((size_t)b * Ln + l0 + _r) * Ln + (size_t)_k * 128 + _q * 8; \
            CP_ASYNC16(sb + AT_P(_s) + _so, g_P_hi + _go); \
            CP_ASYNC16(sb + AT_P(_s) + 16384 + _so, g_P_lo + _go); \
        } \
    } while (0)

    // prologue: groups {P0+Q0}, {Q1}, {Q2}
    REFILL_P(0);
    REFILL_Q(0);
    CP_COMMIT();
    REFILL_Q(1);
    CP_COMMIT();
    REFILL_Q(2);
    CP_COMMIT();

    float acc2[4][8][4];
#pragma unroll
    for (int q = 0; q < 4; q++)
#pragma unroll
        for (int nt = 0; nt < 8; nt++)
#pragma unroll
            for (int j = 0; j < 4; j++) acc2[q][nt][j] = 0.f;

    int a_row_off = ((lane >> 3) & 1) * 8 + (lane & 7);
    int a_half = (lane >> 4) * 16;
    int b_row_off = (lane >> 4) * 8 + (lane & 7);
    int b_half = ((lane >> 3) & 1) * 16;
    uint32_t swl = (uint32_t)(lane & 7) << 4;

    for (int k = 0; k < 32; k++) {
        CP_WAIT2();          // retires {P(k), Q(k,0)}
        __syncthreads();
        REFILL_Q(k * 4 + 3);
        CP_COMMIT();

        // A-fragments: P tile rows (warp's 16 l), K = warp_n's 64 m
        uint32_t Pb = sb + AT_P(k & 1);
        uint32_t afh[4][4], afl[4][4];
#pragma unroll
        for (int ks = 0; ks < 4; ks++) {
            uint32_t row = warp_m * 16 + a_row_off;
            uint32_t ko = (uint32_t)(warp_n * 128 + ks * 32 + a_half);
            uint32_t ad = Pb + row * 256 + (ko ^ swl);
            LDSM_X4(afh[ks][0], afh[ks][1], afh[ks][2], afh[ks][3], ad);
            LDSM_X4(afl[ks][0], afl[ks][1], afl[ks][2], afl[ks][3], ad + 16384);
        }

        // GEMM2 over four gT c-quarters
#pragma unroll
        for (int q = 0; q < 4; q++) {
            if (q > 0) {
                CP_WAIT2();
                __syncthreads();
                REFILL_Q(k * 4 + q + 3);
                if (q == 1) REFILL_P(k + 1);
                CP_COMMIT();
            }
            uint32_t gtb = sb + AT_GTQ(q);
#pragma unroll
            for (int ks = 0; ks < 4; ks++) {
                uint32_t koff = (uint32_t)(warp_n * 128 + ks * 32);
#pragma unroll
                for (int np = 0; np < 4; np++) {
                    uint32_t row = np * 16 + b_row_off;
                    uint32_t ad = gtb + row * 256 + ((koff + (uint32_t)b_half) ^ swl);
                    uint32_t bh[4], bl[4];
                    LDSM_X4(bh[0], bh[1], bh[2], bh[3], ad);
                    LDSM_X4(bl[0], bl[1], bl[2], bl[3], ad + 16384);
                    MMA_BF16(acc2[q][2 * np],     afh[ks], bh[0], bh[1]);
                    MMA_BF16(acc2[q][2 * np],     afh[ks], bl[0], bl[1]);
                    MMA_BF16(acc2[q][2 * np],     afl[ks], bh[0], bh[1]);
                    MMA_BF16(acc2[q][2 * np + 1], afh[ks], bh[2], bh[3]);
                    MMA_BF16(acc2[q][2 * np + 1], afh[ks], bl[2], bl[3]);
                    MMA_BF16(acc2[q][2 * np + 1], afl[ks], bh[2], bh[3]);
                }
            }
        }
    }

    // cross-warp_n (m-split) reduction; write AG as bf16 hi/lo
    CP_WAIT0();
    __syncthreads();
    float* red = (float*)(sm + AT_RED);
    if (warp_n == 1) {
#pragma unroll
        for (int q = 0; q < 4; q++)
#pragma unroll
            for (int nt = 0; nt < 8; nt++) {
                int r = warp_m * 16 + (lane >> 2);
                int c = q * 64 + nt * 8 + 2 * (lane & 3);
                red[r * 260 + c] = acc2[q][nt][0];
                red[r * 260 + c + 1] = acc2[q][nt][1];
                red[(r + 8) * 260 + c] = acc2[q][nt][2];
                red[(r + 8) * 260 + c + 1] = acc2[q][nt][3];
            }
    }
    __syncthreads();
    if (warp_n == 0) {
#pragma unroll
        for (int q = 0; q < 4; q++)
#pragma unroll
            for (int nt = 0; nt < 8; nt++) {
                int rr = warp_m * 16 + (lane >> 2);
                int cc = q * 64 + nt * 8 + 2 * (lane & 3);
                float v00 = acc2[q][nt][0] + red[rr * 260 + cc];
                float v01 = acc2[q][nt][1] + red[rr * 260 + cc + 1];
                float v10 = acc2[q][nt][2] + red[(rr + 8) * 260 + cc];
                float v11 = acc2[q][nt][3] + red[(rr + 8) * 260 + cc + 1];
                __nv_bfloat16 h0, e0, h1, e1;
                size_t o = ((size_t)b * Ln + l0 + rr) * CGn + cc;
                split_bf16(v00, h0, e0); split_bf16(v01, h1, e1);
                *(uint32_t*)((char*)g_ag_hi + o * 2) = packbf(h0, h1);
                *(uint32_t*)((char*)g_ag_lo + o * 2) = packbf(e0, e1);
                o = ((size_t)b * Ln + l0 + rr + 8) * CGn + cc;
                split_bf16(v10, h0, e0); split_bf16(v11, h1, e1);
                *(uint32_t*)((char*)g_ag_hi + o * 2) = packbf(h0, h1);
                *(uint32_t*)((char*)g_ag_lo + o * 2) = packbf(e0, e1);
            }
    }
#undef REFILL_Q
#undef REFILL_P
}

// ===========================================================================
// K5: out-projection + blend via bf16x3 mma (unchanged).
// ===========================================================================
#define F_SMEM 131072

__global__ void __launch_bounds__(256, 1) final_mma(const float* __restrict__ x,
                             const float* __restrict__ Wo, const float* __restrict__ bo,
                             const float* __restrict__ gamma, float* __restrict__ out) {
    extern __shared__ char sm[];
    uint32_t sb = smem_u32(sm);
    int tid = threadIdx.x, lane = tid & 31, wid = tid >> 5;
    int warp_m = wid & 3, warp_n = wid >> 2;
    int c0 = blockIdx.x * 128, l0 = blockIdx.y * 128, b = blockIdx.z;

    const __nv_bfloat16* Ah = g_ag_hi + ((size_t)b * Ln + l0) * CGn;
    const __nv_bfloat16* Al = g_ag_lo + ((size_t)b * Ln + l0) * CGn;

    float4 rw[8];
#pragma unroll
    for (int t = 0; t < 8; t++) {
        int idx = tid + t * 256, r = idx >> 4, q = idx & 15;
        rw[t] = *(const float4*)&Wo[(size_t)(c0 + r) * CGn + q * 4];
    }
#pragma unroll
    for (int t = 0; t < 4; t++) {
        int idx = tid + t * 256, r = idx >> 3, q = idx & 7;
        uint32_t so = r * 128 + ((q * 16) ^ ((r & 7) << 4));
        CP_ASYNC16(sb + 65536 + so, Ah + (size_t)r * CGn + q * 8);
        CP_ASYNC16(sb + 65536 + 16384 + so, Al + (size_t)r * CGn + q * 8);
    }
    CP_COMMIT();

    float acc[2][8][4];
#pragma unroll
    for (int mt = 0; mt < 2; mt++)
#pragma unroll
        for (int nt = 0; nt < 8; nt++)
#pragma unroll
            for (int j = 0; j < 4; j++) acc[mt][nt][j] = 0.f;

    int a_row_off = ((lane >> 3) & 1) * 8 + (lane & 7);
    int a_half = (lane >> 4) * 16;
    int b_row_off = (lane >> 4) * 8 + (lane & 7);
    int b_half = ((lane >> 3) & 1) * 16;
    uint32_t swl = (uint32_t)(lane & 7) << 4;

    for (int kc = 0; kc < 4; kc++) {
        uint32_t wa = sb + (uint32_t)(kc & 1) * 32768;
        uint32_t ba = sb + 65536 + (uint32_t)(kc & 1) * 32768;
#pragma unroll
        for (int t = 0; t < 8; t++) {
            int idx = tid + t * 256, r = idx >> 4, q = idx & 15;
            __nv_bfloat16 h0, e0, h1, e1, h2, e2, h3, e3;
            split_bf16(rw[t].x, h0, e0); split_bf16(rw[t].y, h1, e1);
            split_bf16(rw[t].z, h2, e2); split_bf16(rw[t].w, h3, e3);
            uint32_t so = r * 128 + ((q * 8) ^ ((r & 7) << 4));
            *(uint2*)(sm + (wa - sb) + so) = make_uint2(packbf(h0, h1), packbf(h2, h3));
            *(uint2*)(sm + (wa - sb) + 16384 + so) = make_uint2(packbf(e0, e1), packbf(e2, e3));
        }
        if (kc < 3) {
            int k0n = (kc + 1) * 64;
            uint32_t bn = 65536 + (uint32_t)((kc + 1) & 1) * 32768;
#pragma unroll
            for (int t = 0; t < 4; t++) {
                int idx = tid + t * 256, r = idx >> 3, q = idx & 7;
                uint32_t so = r * 128 + ((q * 16) ^ ((r & 7) << 4));
                CP_ASYNC16(sb + bn + so, Ah + (size_t)r * CGn + k0n + q * 8);
                CP_ASYNC16(sb + bn + 16384 + so, Al + (size_t)r * CGn + k0n + q * 8);
            }
            CP_COMMIT();
            CP_WAIT1();
        } else {
            CP_WAIT0();
        }
        __syncthreads();
        if (kc < 3) {
            int k0n = (kc + 1) * 64;
#pragma unroll
            for (int t = 0; t < 8; t++) {
                int idx = tid + t * 256, r = idx >> 4, q = idx & 15;
                rw[t] = *(const float4*)&Wo[(size_t)(c0 + r) * CGn + k0n + q * 4];
            }
        }
#pragma unroll
        for (int ks = 0; ks < 4; ks++) {
            int koff = ks * 32;
            uint32_t ah[2][4], al[2][4], bh[4][4], bl[4][4];
#pragma unroll
            for (int mt = 0; mt < 2; mt++) {
                uint32_t row = warp_m * 32 + mt * 16 + a_row_off;
                uint32_t ad = wa + row * 128 + (((uint32_t)(koff + a_half)) ^ swl);
                LDSM_X4(ah[mt][0], ah[mt][1], ah[mt][2], ah[mt][3], ad);
                LDSM_X4(al[mt][0], al[mt][1], al[mt][2], al[mt][3], ad + 16384);
            }
#pragma unroll
            for (int np = 0; np < 4; np++) {
                uint32_t row = warp_n * 64 + np * 16 + b_row_off;
                uint32_t ad = ba + row * 128 + (((uint32_t)(koff + b_half)) ^ swl);
                LDSM_X4(bh[np][0], bh[np][1], bh[np][2], bh[np][3], ad);
                LDSM_X4(bl[np][0], bl[np][1], bl[np][2], bl[np][3], ad + 16384);
            }
#pragma unroll
            for (int mt = 0; mt < 2; mt++)
#pragma unroll
                for (int np = 0; np < 4; np++) {
                    MMA_BF16(acc[mt][2 * np],     ah[mt], bh[np][0], bh[np][1]);
                    MMA_BF16(acc[mt][2 * np],     ah[mt], bl[np][0], bl[np][1]);
                    MMA_BF16(acc[mt][2 * np],     al[mt], bh[np][0], bh[np][1]);
                    MMA_BF16(acc[mt][2 * np + 1], ah[mt], bh[np][2], bh[np][3]);
                    MMA_BF16(acc[mt][2 * np + 1], ah[mt], bl[np][2], bl[np][3]);
                    MMA_BF16(acc[mt][2 * np + 1], al[mt], bh[np][2], bh[np][3]);
                }
        }
        __syncthreads();
    }

    float gv = gamma[0];
    float alpha = 1.0f / (1.0f + __expf(-gv));
    float* out1 = out;
    float* out2 = out + (size_t)Bn * Cn * Ln;
#pragma unroll
    for (int mt = 0; mt < 2; mt++)
#pragma unroll
        for (int nt = 0; nt < 8; nt++) {
            int rc = c0 + warp_m * 32 + mt * 16 + (lane >> 2);
            int cl = l0 + warp_n * 64 + nt * 8 + 2 * (lane & 3);
            float bv0 = bo[rc], bv1 = bo[rc + 8];
            size_t base0 = (size_t)b * Cn * Ln + (size_t)rc * Ln + cl;
            size_t base1 = (size_t)b * Cn * Ln + (size_t)(rc + 8) * Ln + cl;
            float2 v0 = make_float2(acc[mt][nt][0] + bv0, acc[mt][nt][1] + bv0);
            float2 v1 = make_float2(acc[mt][nt][2] + bv1, acc[mt][nt][3] + bv1);
            float2 x0 = *(const float2*)&x[base0];
            float2 x1 = *(const float2*)&x[base1];
            *(float2*)&out2[base0] = v0;
            *(float2*)&out2[base1] = v1;
            float2 o0 = make_float2((1.f - alpha) * x0.x + alpha * v0.x,
                                    (1.f - alpha) * x0.y + alpha * v0.y);
            float2 o1 = make_float2((1.f - alpha) * x1.x + alpha * v1.x,
                                    (1.f - alpha) * x1.y + alpha * v1.y);
            *(float2*)&out1[base0] = o0;
            *(float2*)&out1[base1] = o1;
        }
}

extern "C" void kernel_launch(void* const* d_in, const int* in_sizes, int n_in,
                              void* d_out, int out_size) {
    const float* x     = (const float*)d_in[0];
    const float* Wt    = (const float*)d_in[1];
    const float* bt    = (const float*)d_in[2];
    const float* Wp    = (const float*)d_in[3];
    const float* bp    = (const float*)d_in[4];
    const float* Wg    = (const float*)d_in[5];
    const float* bg    = (const float*)d_in[6];
    const float* Wo    = (const float*)d_in[7];
    const float* bo    = (const float*)d_in[8];
    const float* gamma = (const float*)d_in[9];
    float* out = (float*)d_out;

    cudaFuncSetAttribute(proj_mma, cudaFuncAttributeMaxDynamicSharedMemorySize, P_SMEM);
    cudaFuncSetAttribute(softstats_kernel, cudaFuncAttributeMaxDynamicSharedMemorySize, S_SMEM);
    cudaFuncSetAttribute(attn_fused, cudaFuncAttributeMaxDynamicSharedMemorySize, AT_SMEM);
    cudaFuncSetAttribute(final_mma, cudaFuncAttributeMaxDynamicSharedMemorySize, F_SMEM);

    proj_mma<<<dim3(Ln / 128, 3, Bn), 256, P_SMEM>>>(x, Wt, bt, Wp, bp, Wg, bg);
    softstats_kernel<<<dim3(Ln / 128, Bn), 256, S_SMEM>>>();
    transpose_scale_kernel<<<dim3(Ln / 32, CGn / 32, Bn), dim3(32, 8)>>>();
    attn_fused<<<dim3(Ln / 64, Bn), 256, AT_SMEM>>>();
    final_mma<<<dim3(Cn / 128, Ln / 128, Bn), 256, F_SMEM>>>(x, Wo, bo, gamma, out);
}

// round 11
// speedup vs baseline: 1.2635x; 1.2635x over previous
#include <cuda_runtime.h>
#include <cuda_bf16.h>
#include <math.h>
#include <stdint.h>

#define Bn 4
#define Cn 512
#define Ln 4096
#define CKn 64
#define CGn 256

// Scratch (allocation-free rule: static __device__ arrays)
__device__ __nv_bfloat16 g_th_hi[Bn * Ln * CKn];   // theta pre-scaled by log2(e)
__device__ __nv_bfloat16 g_th_lo[Bn * Ln * CKn];
__device__ __nv_bfloat16 g_ph_hi[Bn * Ln * CKn];
__device__ __nv_bfloat16 g_ph_lo[Bn * Ln * CKn];
__device__ float g_gv[Bn * Ln * CGn];
__device__ __nv_bfloat16 g_gt_hi[Bn * CGn * Ln];
__device__ __nv_bfloat16 g_gt_lo[Bn * CGn * Ln];
__device__ float g_colinv[Bn * Ln];
__device__ __nv_bfloat16 g_P[(size_t)Bn * Ln * Ln];  // unnormalized exp2(S'), single bf16
__device__ __nv_bfloat16 g_ag_hi[Bn * Ln * CGn];
__device__ __nv_bfloat16 g_ag_lo[Bn * Ln * CGn];

__device__ __forceinline__ uint32_t smem_u32(const void* p) {
    uint32_t a;
    asm("{ .reg .u64 t; cvta.to.shared.u64 t, %1; cvt.u32.u64 %0, t; }" : "=r"(a) : "l"(p));
    return a;
}

#define LDSM_X4(r0, r1, r2, r3, addr) \
    asm volatile("ldmatrix.sync.aligned.m8n8.x4.shared.b16 {%0,%1,%2,%3}, [%4];" \
                 : "=r"(r0), "=r"(r1), "=r"(r2), "=r"(r3) : "r"(addr))

#define LDSM_X4_T(r0, r1, r2, r3, addr) \
    asm volatile("ldmatrix.sync.aligned.m8n8.x4.trans.shared.b16 {%0,%1,%2,%3}, [%4];" \
                 : "=r"(r0), "=r"(r1), "=r"(r2), "=r"(r3) : "r"(addr))

#define MMA_BF16(d, a, b0, b1) \
    asm volatile("mma.sync.aligned.m16n8k16.row.col.f32.bf16.bf16.f32 " \
                 "{%0,%1,%2,%3},{%4,%5,%6,%7},{%8,%9},{%0,%1,%2,%3};" \
                 : "+f"((d)[0]), "+f"((d)[1]), "+f"((d)[2]), "+f"((d)[3]) \
                 : "r"((a)[0]), "r"((a)[1]), "r"((a)[2]), "r"((a)[3]), "r"(b0), "r"(b1))

#define CP_ASYNC16(smem, gptr) \
    asm volatile("cp.async.cg.shared.global [%0], [%1], 16;" :: "r"(smem), "l"(gptr))
#define CP_COMMIT() asm volatile("cp.async.commit_group;")
#define CP_WAIT0()  asm volatile("cp.async.wait_group 0;")
#define CP_WAIT1()  asm volatile("cp.async.wait_group 1;")
#define CP_WAIT2()  asm volatile("cp.async.wait_group 2;")

__device__ __forceinline__ void split_bf16(float f, __nv_bfloat16& hi, __nv_bfloat16& lo) {
    hi = __float2bfloat16(f);
    lo = __float2bfloat16(f - __bfloat162float(hi));
}
__device__ __forceinline__ uint32_t packbf(__nv_bfloat16 a, __nv_bfloat16 b) {
    return ((uint32_t)__bfloat16_as_ushort(b) << 16) | __bfloat16_as_ushort(a);
}
__device__ __forceinline__ float ex2f(float x) {
    float r;
    asm("ex2.approx.f32 %0, %1;" : "=f"(r) : "f"(x));
    return r;
}

// ===========================================================================
// K1: projections via bf16x3 mma. theta scaled by log2(e) (ex2 softmax).
// ===========================================================================
#define P_SMEM 131072

__global__ void __launch_bounds__(256, 1) proj_mma(const float* __restrict__ x,
                            const float* __restrict__ Wt, const float* __restrict__ bt,
                            const float* __restrict__ Wp, const float* __restrict__ bp,
                            const float* __restrict__ Wg, const float* __restrict__ bg) {
    extern __shared__ char sm[];
    uint32_t sb = smem_u32(sm);
    int tid = threadIdx.x, lane = tid & 31, wid = tid >> 5;
    int warp_m = wid & 3, warp_n = wid >> 2;
    int l0 = blockIdx.x * 128, grp = blockIdx.y, b = blockIdx.z;
    const float* xb = x + (size_t)b * Cn * Ln;

    float4 rx[8], rw[8];
#pragma unroll
    for (int t = 0; t < 8; t++) {
        int idx = tid + t * 256, r = idx >> 5, q = idx & 31;
        rx[t] = *(const float4*)&xb[(size_t)r * Ln + l0 + q * 4];
    }
#pragma unroll
    for (int t = 0; t < 8; t++) {
        int idx = tid + t * 256, r = idx >> 4, q = idx & 15;
        const float* Wrow;
        if (grp == 0) Wrow = (r < 64) ? Wt + (size_t)r * Cn : Wp + (size_t)(r - 64) * Cn;
        else          Wrow = Wg + (size_t)((grp - 1) * 128 + r) * Cn;
        rw[t] = *(const float4*)&Wrow[q * 4];
    }

    float acc[2][8][4];
#pragma unroll
    for (int mt = 0; mt < 2; mt++)
#pragma unroll
        for (int nt = 0; nt < 8; nt++)
#pragma unroll
            for (int j = 0; j < 4; j++) acc[mt][nt][j] = 0.f;

    int b_row_off = (lane >> 4) * 8 + (lane & 7);
    int b_half = ((lane >> 3) & 1) * 16;
    uint32_t swl = (uint32_t)(lane & 7) << 4;

    for (int kc = 0; kc < 8; kc++) {
        uint32_t xa = sb + (uint32_t)(kc & 1) * 32768;
        uint32_t wb = sb + 65536 + (uint32_t)(kc & 1) * 32768;
#pragma unroll
        for (int t = 0; t < 8; t++) {
            int idx = tid + t * 256, r = idx >> 5, q = idx & 31;
            __nv_bfloat16 h0, e0, h1, e1, h2, e2, h3, e3;
            split_bf16(rx[t].x, h0, e0); split_bf16(rx[t].y, h1, e1);
            split_bf16(rx[t].z, h2, e2); split_bf16(rx[t].w, h3, e3);
            uint32_t so = r * 256 + ((q * 8) ^ ((r & 7) << 4));
            *(uint2*)(sm + (xa - sb) + so) = make_uint2(packbf(h0, h1), packbf(h2, h3));
            *(uint2*)(sm + (xa - sb) + 16384 + so) = make_uint2(packbf(e0, e1), packbf(e2, e3));
        }
#pragma unroll
        for (int t = 0; t < 8; t++) {
            int idx = tid + t * 256, r = idx >> 4, q = idx & 15;
            __nv_bfloat16 h0, e0, h1, e1, h2, e2, h3, e3;
            split_bf16(rw[t].x, h0, e0); split_bf16(rw[t].y, h1, e1);
            split_bf16(rw[t].z, h2, e2); split_bf16(rw[t].w, h3, e3);
            uint32_t so = r * 128 + ((q * 8) ^ ((r & 7) << 4));
            *(uint2*)(sm + (wb - sb) + so) = make_uint2(packbf(h0, h1), packbf(h2, h3));
            *(uint2*)(sm + (wb - sb) + 16384 + so) = make_uint2(packbf(e0, e1), packbf(e2, e3));
        }
        __syncthreads();
        if (kc < 7) {
            int k0n = (kc + 1) * 64;
#pragma unroll
            for (int t = 0; t < 8; t++) {
                int idx = tid + t * 256, r = idx >> 5, q = idx & 31;
                rx[t] = *(const float4*)&xb[(size_t)(k0n + r) * Ln + l0 + q * 4];
            }
#pragma unroll
            for (int t = 0; t < 8; t++) {
                int idx = tid + t * 256, r = idx >> 4, q = idx & 15;
                const float* Wrow;
                if (grp == 0) Wrow = (r < 64) ? Wt + (size_t)r * Cn : Wp + (size_t)(r - 64) * Cn;
                else          Wrow = Wg + (size_t)((grp - 1) * 128 + r) * Cn;
                rw[t] = *(const float4*)&Wrow[k0n + q * 4];
            }
        }
#pragma unroll
        for (int ks = 0; ks < 4; ks++) {
            uint32_t ah[2][4], al[2][4], bh[4][4], bl[4][4];
            uint32_t srow = (uint32_t)(ks * 16 + (lane & 7) + ((lane >> 4) & 1) * 8);
#pragma unroll
            for (int mt = 0; mt < 2; mt++) {
                uint32_t mb = (uint32_t)(warp_m * 32 + mt * 16 + ((lane >> 3) & 1) * 8) * 2;
                uint32_t ad = xa + srow * 256 + (mb ^ swl);
                LDSM_X4_T(ah[mt][0], ah[mt][1], ah[mt][2], ah[mt][3], ad);
                LDSM_X4_T(al[mt][0], al[mt][1], al[mt][2], al[mt][3], ad + 16384);
            }
#pragma unroll
            for (int np = 0; np < 4; np++) {
                uint32_t row = (uint32_t)(warp_n * 64 + np * 16 + b_row_off);
                uint32_t ad = wb + row * 128 + (((uint32_t)(ks * 32 + b_half)) ^ swl);
                LDSM_X4(bh[np][0], bh[np][1], bh[np][2], bh[np][3], ad);
                LDSM_X4(bl[np][0], bl[np][1], bl[np][2], bl[np][3], ad + 16384);
            }
#pragma unroll
            for (int mt = 0; mt < 2; mt++)
#pragma unroll
                for (int np = 0; np < 4; np++) {
                    MMA_BF16(acc[mt][2 * np],     ah[mt], bh[np][0], bh[np][1]);
                    MMA_BF16(acc[mt][2 * np],     ah[mt], bl[np][0], bl[np][1]);
                    MMA_BF16(acc[mt][2 * np],     al[mt], bh[np][0], bh[np][1]);
                    MMA_BF16(acc[mt][2 * np + 1], ah[mt], bh[np][2], bh[np][3]);
                    MMA_BF16(acc[mt][2 * np + 1], ah[mt], bl[np][2], bl[np][3]);
                    MMA_BF16(acc[mt][2 * np + 1], al[mt], bh[np][2], bh[np][3]);
                }
        }
        __syncthreads();
    }

    if (grp == 0) {
        __nv_bfloat16* ohi = (warp_n == 0 ? g_th_hi : g_ph_hi) + (size_t)b * Ln * CKn;
        __nv_bfloat16* olo = (warp_n == 0 ? g_th_lo : g_ph_lo) + (size_t)b * Ln * CKn;
        const float* bias = (warp_n == 0 ? bt : bp);
        float sc = (warp_n == 0) ? 1.4426950408889634f : 1.0f;  // log2(e) for theta
#pragma unroll
        for (int mt = 0; mt < 2; mt++)
#pragma unroll
            for (int nt = 0; nt < 8; nt++) {
                int r = warp_m * 32 + mt * 16 + (lane >> 2);
                int cl = nt * 8 + 2 * (lane & 3);
                float bv0 = bias[cl], bv1 = bias[cl + 1];
                float v00 = tanhf(acc[mt][nt][0] + bv0) * sc;
                float v01 = tanhf(acc[mt][nt][1] + bv1) * sc;
                float v10 = tanhf(acc[mt][nt][2] + bv0) * sc;
                float v11 = tanhf(acc[mt][nt][3] + bv1) * sc;
                __nv_bfloat16 h0, e0, h1, e1;
                split_bf16(v00, h0, e0); split_bf16(v01, h1, e1);
                size_t o = (size_t)(l0 + r) * CKn + cl;
                *(uint32_t*)((char*)ohi + o * 2) = packbf(h0, h1);
                *(uint32_t*)((char*)olo + o * 2) = packbf(e0, e1);
                split_bf16(v10, h0, e0); split_bf16(v11, h1, e1);
                o = (size_t)(l0 + r + 8) * CKn + cl;
                *(uint32_t*)((char*)ohi + o * 2) = packbf(h0, h1);
                *(uint32_t*)((char*)olo + o * 2) = packbf(e0, e1);
            }
    } else {
        float* outp = g_gv + (size_t)b * Ln * CGn;
        int goff = (grp - 1) * 128 + warp_n * 64;
#pragma unroll
        for (int mt = 0; mt < 2; mt++)
#pragma unroll
            for (int nt = 0; nt < 8; nt++) {
                int r = warp_m * 32 + mt * 16 + (lane >> 2);
                int cl = nt * 8 + 2 * (lane & 3);
                int c = goff + cl;
                float bv0 = bg[c], bv1 = bg[c + 1];
                float2 v0 = make_float2(acc[mt][nt][0] + bv0, acc[mt][nt][1] + bv1);
                float2 v1 = make_float2(acc[mt][nt][2] + bv0, acc[mt][nt][3] + bv1);
                *(float2*)&outp[(size_t)(l0 + r) * CGn + c] = v0;
                *(float2*)&outp[(size_t)(l0 + r + 8) * CGn + c] = v1;
            }
    }
}

// ===========================================================================
// K2: softstats — computes S once, emits P = exp2(S') (single bf16, 268 MB)
// and per-column sums. 4-deep theta ring: one sync per chunk.
// ===========================================================================
#define S_PH 0
#define S_TH(s) (32768 + (s) * 32768)
#define S_WSM   163840
#define S_SMEM  165888

__global__ void __launch_bounds__(256, 1) softstats_kernel() {
    extern __shared__ char sm[];
    uint32_t sb = smem_u32(sm);
    int tid = threadIdx.x;
    int lane = tid & 31, wid = tid >> 5;
    int warp_m = wid & 3, warp_n = wid >> 2;
    int m0 = blockIdx.x * 128, b = blockIdx.y;

    const __nv_bfloat16* thh = g_th_hi + (size_t)b * Ln * CKn;
    const __nv_bfloat16* thl = g_th_lo + (size_t)b * Ln * CKn;
    const __nv_bfloat16* phh = g_ph_hi + (size_t)b * Ln * CKn;
    const __nv_bfloat16* phl = g_ph_lo + (size_t)b * Ln * CKn;

#pragma unroll
    for (int s = 0; s < 3; s++) {
#pragma unroll
        for (int t = 0; t < 4; t++) {
            int idx = tid + t * 256;
            int r = idx >> 3, q = idx & 7;
            uint32_t so = r * 128 + ((q * 16) ^ ((r & 7) << 4));
            CP_ASYNC16(sb + S_TH(s) + so, thh + ((size_t)(s * 128 + r)) * CKn + q * 8);
            CP_ASYNC16(sb + S_TH(s) + 16384 + so, thl + ((size_t)(s * 128 + r)) * CKn + q * 8);
        }
        CP_COMMIT();
    }
#pragma unroll
    for (int t = 0; t < 4; t++) {
        int idx = tid + t * 256;
        int r = idx >> 3, q = idx & 7;
        uint32_t so = r * 128 + ((q * 16) ^ ((r & 7) << 4));
        *(uint4*)(sm + S_PH + so) = *(const uint4*)(phh + ((size_t)(m0 + r)) * CKn + q * 8);
        *(uint4*)(sm + S_PH + 16384 + so) = *(const uint4*)(phl + ((size_t)(m0 + r)) * CKn + q * 8);
    }

    float sum[16];
#pragma unroll
    for (int i = 0; i < 16; i++) sum[i] = 0.f;

    int a_row_off = ((lane >> 3) & 1) * 8 + (lane & 7);
    int a_half = (lane >> 4) * 16;
    int b_row_off = (lane >> 4) * 8 + (lane & 7);
    int b_half = ((lane >> 3) & 1) * 16;
    uint32_t swl = (uint32_t)(lane & 7) << 4;

    for (int lc = 0; lc < 32; lc++) {
        CP_WAIT2();
        __syncthreads();
        {
            int ln = (lc + 3) & 31;
            uint32_t bufo = S_TH((lc + 3) & 3);
#pragma unroll
            for (int t = 0; t < 4; t++) {
                int idx = tid + t * 256;
                int r = idx >> 3, q = idx & 7;
                uint32_t so = r * 128 + ((q * 16) ^ ((r & 7) << 4));
                CP_ASYNC16(sb + bufo + so, thh + ((size_t)(ln * 128 + r)) * CKn + q * 8);
                CP_ASYNC16(sb + bufo + 16384 + so, thl + ((size_t)(ln * 128 + r)) * CKn + q * 8);
            }
            CP_COMMIT();
        }
        uint32_t thb = sb + S_TH(lc & 3);
        float acc[2][8][4];
#pragma unroll
        for (int mt = 0; mt < 2; mt++)
#pragma unroll
            for (int nt = 0; nt < 8; nt++)
#pragma unroll
                for (int j = 0; j < 4; j++) acc[mt][nt][j] = 0.f;

#pragma unroll
        for (int ks = 0; ks < 4; ks++) {
            int koff = ks * 32;
            uint32_t ah[2][4], al[2][4], bh[4][4], bl[4][4];
#pragma unroll
            for (int mt = 0; mt < 2; mt++) {
                uint32_t row = warp_m * 32 + mt * 16 + a_row_off;
                uint32_t ad = thb + row * 128 + (((uint32_t)(koff + a_half)) ^ swl);
                LDSM_X4(ah[mt][0], ah[mt][1], ah[mt][2], ah[mt][3], ad);
                LDSM_X4(al[mt][0], al[mt][1], al[mt][2], al[mt][3], ad + 16384);
            }
#pragma unroll
            for (int np = 0; np < 4; np++) {
                uint32_t row = warp_n * 64 + np * 16 + b_row_off;
                uint32_t ad = sb + S_PH + row * 128 + (((uint32_t)(koff + b_half)) ^ swl);
                LDSM_X4(bh[np][0], bh[np][1], bh[np][2], bh[np][3], ad);
                LDSM_X4(bl[np][0], bl[np][1], bl[np][2], bl[np][3], ad + 16384);
            }
#pragma unroll
            for (int mt = 0; mt < 2; mt++)
#pragma unroll
                for (int np = 0; np < 4; np++) {
                    MMA_BF16(acc[mt][2 * np],     ah[mt], bh[np][0], bh[np][1]);
                    MMA_BF16(acc[mt][2 * np],     ah[mt], bl[np][0], bl[np][1]);
                    MMA_BF16(acc[mt][2 * np],     al[mt], bh[np][0], bh[np][1]);
                    MMA_BF16(acc[mt][2 * np + 1], ah[mt], bh[np][2], bh[np][3]);
                    MMA_BF16(acc[mt][2 * np + 1], ah[mt], bl[np][2], bl[np][3]);
                    MMA_BF16(acc[mt][2 * np + 1], al[mt], bh[np][2], bh[np][3]);
                }
        }
        // exp2 -> column sums + P store (single bf16)
#pragma unroll
        for (int mt = 0; mt < 2; mt++)
#pragma unroll
            for (int nt = 0; nt < 8; nt++) {
                float e0 = ex2f(acc[mt][nt][0]);
                float e1 = ex2f(acc[mt][nt][1]);
                float e2 = ex2f(acc[mt][nt][2]);
                float e3 = ex2f(acc[mt][nt][3]);
                sum[nt * 2]     += e0 + e2;
                sum[nt * 2 + 1] += e1 + e3;
                int lrow = lc * 128 + warp_m * 32 + mt * 16 + (lane >> 2);
                int mcol = m0 + warp_n * 64 + nt * 8 + 2 * (lane & 3);
                size_t o = ((size_t)b * Ln + lrow) * Ln + mcol;
                *(uint32_t*)((char*)g_P + o * 2) =
                    packbf(__float2bfloat16(e0), __float2bfloat16(e1));
                o += (size_t)8 * Ln;
                *(uint32_t*)((char*)g_P + o * 2) =
                    packbf(__float2bfloat16(e2), __float2bfloat16(e3));
            }
    }

#pragma unroll
    for (int s = 4; s <= 16; s <<= 1)
#pragma unroll
        for (int i = 0; i < 16; i++)
            sum[i] += __shfl_xor_sync(0xffffffffu, sum[i], s);

    float* wsm = (float*)(sm + S_WSM);
    __syncthreads();
    if (lane < 4) {
#pragma unroll
        for (int nt = 0; nt < 8; nt++)
#pragma unroll
            for (int j = 0; j < 2; j++) {
                int c = warp_n * 64 + nt * 8 + 2 * lane + j;
                wsm[warp_m * 128 + c] = sum[nt * 2 + j];
            }
    }
    __syncthreads();
    if (tid < 128) {
        float S = 0.f;
#pragma unroll
        for (int w = 0; w < 4; w++) S += wsm[w * 128 + tid];
        g_colinv[b * Ln + m0 + tid] = 1.0f / S;
    }
}

// ===========================================================================
// K3: gT transpose+scale (unchanged).
// ===========================================================================
__global__ void transpose_scale_kernel() {
    __shared__ float t[32][33];
    int m0 = blockIdx.x * 32, c0 = blockIdx.y * 32, b = blockIdx.z;
    int tx = threadIdx.x, ty = threadIdx.y;
#pragma unroll
    for (int i = 0; i < 32; i += 8) {
        int m = m0 + ty + i;
        t[ty + i][tx] = g_gv[((size_t)b * Ln + m) * CGn + c0 + tx] * g_colinv[b * Ln + m];
    }
    __syncthreads();
#pragma unroll
    for (int i = 0; i < 32; i += 8) {
        float v = t[tx][ty + i];
        __nv_bfloat16 hi, lo;
        split_bf16(v, hi, lo);
        size_t o = ((size_t)b * CGn + c0 + ty + i) * Ln + m0 + tx;
        g_gt_hi[o] = hi;
        g_gt_lo[o] = lo;
    }
}

// ===========================================================================
// K4: attention GEMM2 only: AG = P @ gT^T, P (single bf16) streamed via
// cp.async, gT 4-quarter ring. CTA 64l x 256c, warp_n splits m (K).
// SMEM: P stage s at s*16384; GT quarter q at 32768+q*32768. Total 163840.
// ===========================================================================
#define AT_P(s)   ((s) * 16384)
#define AT_GTQ(q) (32768 + (q) * 32768)
#define AT_RED    0
#define AT_SMEM   163840

__global__ void __launch_bounds__(256, 1) attn_fused() {
    extern __shared__ char sm[];
    uint32_t sb = smem_u32(sm);
    int tid = threadIdx.x;
    int lane = tid & 31, wid = tid >> 5;
    int warp_m = wid & 3, warp_n = wid >> 2;
    int l0 = blockIdx.x * 64, b = blockIdx.y;

    const __nv_bfloat16* Gh = g_gt_hi + (size_t)b * CGn * Ln;
    const __nv_bfloat16* Gl = g_gt_lo + (size_t)b * CGn * Ln;

#define REFILL_Q(Q) do { \
        int _kq = ((Q) >> 2) & 31, _cq = (Q) & 3; \
        uint32_t _bo = AT_GTQ(_cq); \
        _Pragma("unroll") \
        for (int _t = 0; _t < 4; _t++) { \
            int _idx = tid + _t * 256, _r = _idx >> 4, _q = _idx & 15; \
            uint32_t _so = _r * 256 + ((_q * 16) ^ ((_r & 7) << 4)); \
            CP_ASYNC16(sb + _bo + _so, Gh + (size_t)(_cq * 64 + _r) * Ln + _kq * 128 + _q * 8); \
            CP_ASYNC16(sb + _bo + 16384 + _so, Gl + (size_t)(_cq * 64 + _r) * Ln + _kq * 128 + _q * 8); \
        } \
    } while (0)
#define REFILL_P(K) do { \
        int _k = (K) & 31, _s = (K) & 1; \
        _Pragma("unroll") \
        for (int _t = 0; _t < 4; _t++) { \
            int _idx = tid + _t * 256, _r = _idx >> 4, _q = _idx & 15; \
            uint32_t _so = _r * 256 + ((_q * 16) ^ ((_r & 7) << 4)); \
            size_t _go = ((size_t)b * Ln + l0 + _r) * Ln + (size_t)_k * 128 + _q * 8; \
            CP_ASYNC16(sb + AT_P(_s) + _so, g_P + _go); \
        } \
    } while (0)

    // prologue: groups {P0+Q0}, {Q1}, {Q2}
    REFILL_P(0);
    REFILL_Q(0);
    CP_COMMIT();
    REFILL_Q(1);
    CP_COMMIT();
    REFILL_Q(2);
    CP_COMMIT();

    float acc2[4][8][4];
#pragma unroll
    for (int q = 0; q < 4; q++)
#pragma unroll
        for (int nt = 0; nt < 8; nt++)
#pragma unroll
            for (int j = 0; j < 4; j++) acc2[q][nt][j] = 0.f;

    int a_row_off = ((lane >> 3) & 1) * 8 + (lane & 7);
    int a_half = (lane >> 4) * 16;
    int b_row_off = (lane >> 4) * 8 + (lane & 7);
    int b_half = ((lane >> 3) & 1) * 16;
    uint32_t swl = (uint32_t)(lane & 7) << 4;

    for (int k = 0; k < 32; k++) {
        CP_WAIT2();          // retires {P(k), Q(k,0)}
        __syncthreads();
        REFILL_Q(k * 4 + 3);
        CP_COMMIT();

        // A-fragments: P tile rows (warp's 16 l), K = warp_n's 64 m
        uint32_t Pb = sb + AT_P(k & 1);
        uint32_t afh[4][4];
#pragma unroll
        for (int ks = 0; ks < 4; ks++) {
            uint32_t row = warp_m * 16 + a_row_off;
            uint32_t ko = (uint32_t)(warp_n * 128 + ks * 32 + a_half);
            uint32_t ad = Pb + row * 256 + (ko ^ swl);
            LDSM_X4(afh[ks][0], afh[ks][1], afh[ks][2], afh[ks][3], ad);
        }

        // GEMM2 over four gT c-quarters (2-term bf16: P_hi x (g_hi + g_lo))
#pragma unroll
        for (int q = 0; q < 4; q++) {
            if (q > 0) {
                CP_WAIT2();
                __syncthreads();
                REFILL_Q(k * 4 + q + 3);
                if (q == 1) REFILL_P(k + 1);
                CP_COMMIT();
            }
            uint32_t gtb = sb + AT_GTQ(q);
#pragma unroll
            for (int ks = 0; ks < 4; ks++) {
                uint32_t koff = (uint32_t)(warp_n * 128 + ks * 32);
#pragma unroll
                for (int np = 0; np < 4; np++) {
                    uint32_t row = np * 16 + b_row_off;
                    uint32_t ad = gtb + row * 256 + ((koff + (uint32_t)b_half) ^ swl);
                    uint32_t bh[4], bl[4];
                    LDSM_X4(bh[0], bh[1], bh[2], bh[3], ad);
                    LDSM_X4(bl[0], bl[1], bl[2], bl[3], ad + 16384);
                    MMA_BF16(acc2[q][2 * np],     afh[ks], bh[0], bh[1]);
                    MMA_BF16(acc2[q][2 * np],     afh[ks], bl[0], bl[1]);
                    MMA_BF16(acc2[q][2 * np + 1], afh[ks], bh[2], bh[3]);
                    MMA_BF16(acc2[q][2 * np + 1], afh[ks], bl[2], bl[3]);
                }
            }
        }
    }

    // cross-warp_n (m-split) reduction; write AG as bf16 hi/lo
    CP_WAIT0();
    __syncthreads();
    float* red = (float*)(sm + AT_RED);
    if (warp_n == 1) {
#pragma unroll
        for (int q = 0; q < 4; q++)
#pragma unroll
            for (int nt = 0; nt < 8; nt++) {
                int r = warp_m * 16 + (lane >> 2);
                int c = q * 64 + nt * 8 + 2 * (lane & 3);
                red[r * 260 + c] = acc2[q][nt][0];
                red[r * 260 + c + 1] = acc2[q][nt][1];
                red[(r + 8) * 260 + c] = acc2[q][nt][2];
                red[(r + 8) * 260 + c + 1] = acc2[q][nt][3];
            }
    }
    __syncthreads();
    if (warp_n == 0) {
#pragma unroll
        for (int q = 0; q < 4; q++)
#pragma unroll
            for (int nt = 0; nt < 8; nt++) {
                int rr = warp_m * 16 + (lane >> 2);
                int cc = q * 64 + nt * 8 + 2 * (lane & 3);
                float v00 = acc2[q][nt][0] + red[rr * 260 + cc];
                float v01 = acc2[q][nt][1] + red[rr * 260 + cc + 1];
                float v10 = acc2[q][nt][2] + red[(rr + 8) * 260 + cc];
                float v11 = acc2[q][nt][3] + red[(rr + 8) * 260 + cc + 1];
                __nv_bfloat16 h0, e0, h1, e1;
                size_t o = ((size_t)b * Ln + l0 + rr) * CGn + cc;
                split_bf16(v00, h0, e0); split_bf16(v01, h1, e1);
                *(uint32_t*)((char*)g_ag_hi + o * 2) = packbf(h0, h1);
                *(uint32_t*)((char*)g_ag_lo + o * 2) = packbf(e0, e1);
                o = ((size_t)b * Ln + l0 + rr + 8) * CGn + cc;
                split_bf16(v10, h0, e0); split_bf16(v11, h1, e1);
                *(uint32_t*)((char*)g_ag_hi + o * 2) = packbf(h0, h1);
                *(uint32_t*)((char*)g_ag_lo + o * 2) = packbf(e0, e1);
            }
    }
#undef REFILL_Q
#undef REFILL_P
}

// ===========================================================================
// K5: out-projection + blend via bf16x3 mma (unchanged).
// ===========================================================================
#define F_SMEM 131072

__global__ void __launch_bounds__(256, 1) final_mma(const float* __restrict__ x,
                             const float* __restrict__ Wo, const float* __restrict__ bo,
                             const float* __restrict__ gamma, float* __restrict__ out) {
    extern __shared__ char sm[];
    uint32_t sb = smem_u32(sm);
    int tid = threadIdx.x, lane = tid & 31, wid = tid >> 5;
    int warp_m = wid & 3, warp_n = wid >> 2;
    int c0 = blockIdx.x * 128, l0 = blockIdx.y * 128, b = blockIdx.z;

    const __nv_bfloat16* Ah = g_ag_hi + ((size_t)b * Ln + l0) * CGn;
    const __nv_bfloat16* Al = g_ag_lo + ((size_t)b * Ln + l0) * CGn;

    float4 rw[8];
#pragma unroll
    for (int t = 0; t < 8; t++) {
        int idx = tid + t * 256, r = idx >> 4, q = idx & 15;
        rw[t] = *(const float4*)&Wo[(size_t)(c0 + r) * CGn + q * 4];
    }
#pragma unroll
    for (int t = 0; t < 4; t++) {
        int idx = tid + t * 256, r = idx >> 3, q = idx & 7;
        uint32_t so = r * 128 + ((q * 16) ^ ((r & 7) << 4));
        CP_ASYNC16(sb + 65536 + so, Ah + (size_t)r * CGn + q * 8);
        CP_ASYNC16(sb + 65536 + 16384 + so, Al + (size_t)r * CGn + q * 8);
    }
    CP_COMMIT();

    float acc[2][8][4];
#pragma unroll
    for (int mt = 0; mt < 2; mt++)
#pragma unroll
        for (int nt = 0; nt < 8; nt++)
#pragma unroll
            for (int j = 0; j < 4; j++) acc[mt][nt][j] = 0.f;

    int a_row_off = ((lane >> 3) & 1) * 8 + (lane & 7);
    int a_half = (lane >> 4) * 16;
    int b_row_off = (lane >> 4) * 8 + (lane & 7);
    int b_half = ((lane >> 3) & 1) * 16;
    uint32_t swl = (uint32_t)(lane & 7) << 4;

    for (int kc = 0; kc < 4; kc++) {
        uint32_t wa = sb + (uint32_t)(kc & 1) * 32768;
        uint32_t ba = sb + 65536 + (uint32_t)(kc & 1) * 32768;
#pragma unroll
        for (int t = 0; t < 8; t++) {
            int idx = tid + t * 256, r = idx >> 4, q = idx & 15;
            __nv_bfloat16 h0, e0, h1, e1, h2, e2, h3, e3;
            split_bf16(rw[t].x, h0, e0); split_bf16(rw[t].y, h1, e1);
            split_bf16(rw[t].z, h2, e2); split_bf16(rw[t].w, h3, e3);
            uint32_t so = r * 128 + ((q * 8) ^ ((r & 7) << 4));
            *(uint2*)(sm + (wa - sb) + so) = make_uint2(packbf(h0, h1), packbf(h2, h3));
            *(uint2*)(sm + (wa - sb) + 16384 + so) = make_uint2(packbf(e0, e1), packbf(e2, e3));
        }
        if (kc < 3) {
            int k0n = (kc + 1) * 64;
            uint32_t bn = 65536 + (uint32_t)((kc + 1) & 1) * 32768;
#pragma unroll
            for (int t = 0; t < 4; t++) {
                int idx = tid + t * 256, r = idx >> 3, q = idx & 7;
                uint32_t so = r * 128 + ((q * 16) ^ ((r & 7) << 4));
                CP_ASYNC16(sb + bn + so, Ah + (size_t)r * CGn + k0n + q * 8);
                CP_ASYNC16(sb + bn + 16384 + so, Al + (size_t)r * CGn + k0n + q * 8);
            }
            CP_COMMIT();
            CP_WAIT1();
        } else {
            CP_WAIT0();
        }
        __syncthreads();
        if (kc < 3) {
            int k0n = (kc + 1) * 64;
#pragma unroll
            for (int t = 0; t < 8; t++) {
                int idx = tid + t * 256, r = idx >> 4, q = idx & 15;
                rw[t] = *(const float4*)&Wo[(size_t)(c0 + r) * CGn + k0n + q * 4];
            }
        }
#pragma unroll
        for (int ks = 0; ks < 4; ks++) {
            int koff = ks * 32;
            uint32_t ah[2][4], al[2][4], bh[4][4], bl[4][4];
#pragma unroll
            for (int mt = 0; mt < 2; mt++) {
                uint32_t row = warp_m * 32 + mt * 16 + a_row_off;
                uint32_t ad = wa + row * 128 + (((uint32_t)(koff + a_half)) ^ swl);
                LDSM_X4(ah[mt][0], ah[mt][1], ah[mt][2], ah[mt][3], ad);
                LDSM_X4(al[mt][0], al[mt][1], al[mt][2], al[mt][3], ad + 16384);
            }
#pragma unroll
            for (int np = 0; np < 4; np++) {
                uint32_t row = warp_n * 64 + np * 16 + b_row_off;
                uint32_t ad = ba + row * 128 + (((uint32_t)(koff + b_half)) ^ swl);
                LDSM_X4(bh[np][0], bh[np][1], bh[np][2], bh[np][3], ad);
                LDSM_X4(bl[np][0], bl[np][1], bl[np][2], bl[np][3], ad + 16384);
            }
#pragma unroll
            for (int mt = 0; mt < 2; mt++)
#pragma unroll
                for (int np = 0; np < 4; np++) {
                    MMA_BF16(acc[mt][2 * np],     ah[mt], bh[np][0], bh[np][1]);
                    MMA_BF16(acc[mt][2 * np],     ah[mt], bl[np][0], bl[np][1]);
                    MMA_BF16(acc[mt][2 * np],     al[mt], bh[np][0], bh[np][1]);
                    MMA_BF16(acc[mt][2 * np + 1], ah[mt], bh[np][2], bh[np][3]);
                    MMA_BF16(acc[mt][2 * np + 1], ah[mt], bl[np][2], bl[np][3]);
                    MMA_BF16(acc[mt][2 * np + 1], al[mt], bh[np][2], bh[np][3]);
                }
        }
        __syncthreads();
    }

    float gv = gamma[0];
    float alpha = 1.0f / (1.0f + __expf(-gv));
    float* out1 = out;
    float* out2 = out + (size_t)Bn * Cn * Ln;
#pragma unroll
    for (int mt = 0; mt < 2; mt++)
#pragma unroll
        for (int nt = 0; nt < 8; nt++) {
            int rc = c0 + warp_m * 32 + mt * 16 + (lane >> 2);
            int cl = l0 + warp_n * 64 + nt * 8 + 2 * (lane & 3);
            float bv0 = bo[rc], bv1 = bo[rc + 8];
            size_t base0 = (size_t)b * Cn * Ln + (size_t)rc * Ln + cl;
            size_t base1 = (size_t)b * Cn * Ln + (size_t)(rc + 8) * Ln + cl;
            float2 v0 = make_float2(acc[mt][nt][0] + bv0, acc[mt][nt][1] + bv0);
            float2 v1 = make_float2(acc[mt][nt][2] + bv1, acc[mt][nt][3] + bv1);
            float2 x0 = *(const float2*)&x[base0];
            float2 x1 = *(const float2*)&x[base1];
            *(float2*)&out2[base0] = v0;
            *(float2*)&out2[base1] = v1;
            float2 o0 = make_float2((1.f - alpha) * x0.x + alpha * v0.x,
                                    (1.f - alpha) * x0.y + alpha * v0.y);
            float2 o1 = make_float2((1.f - alpha) * x1.x + alpha * v1.x,
                                    (1.f - alpha) * x1.y + alpha * v1.y);
            *(float2*)&out1[base0] = o0;
            *(float2*)&out1[base1] = o1;
        }
}

extern "C" void kernel_launch(void* const* d_in, const int* in_sizes, int n_in,
                              void* d_out, int out_size) {
    const float* x     = (const float*)d_in[0];
    const float* Wt    = (const float*)d_in[1];
    const float* bt    = (const float*)d_in[2];
    const float* Wp    = (const float*)d_in[3];
    const float* bp    = (const float*)d_in[4];
    const float* Wg    = (const float*)d_in[5];
    const float* bg    = (const float*)d_in[6];
    const float* Wo    = (const float*)d_in[7];
    const float* bo    = (const float*)d_in[8];
    const float* gamma = (const float*)d_in[9];
    float* out = (float*)d_out;

    cudaFuncSetAttribute(proj_mma, cudaFuncAttributeMaxDynamicSharedMemorySize, P_SMEM);
    cudaFuncSetAttribute(softstats_kernel, cudaFuncAttributeMaxDynamicSharedMemorySize, S_SMEM);
    cudaFuncSetAttribute(attn_fused, cudaFuncAttributeMaxDynamicSharedMemorySize, AT_SMEM);
    cudaFuncSetAttribute(final_mma, cudaFuncAttributeMaxDynamicSharedMemorySize, F_SMEM);

    proj_mma<<<dim3(Ln / 128, 3, Bn), 256, P_SMEM>>>(x, Wt, bt, Wp, bp, Wg, bg);
    softstats_kernel<<<dim3(Ln / 128, Bn), 256, S_SMEM>>>();
    transpose_scale_kernel<<<dim3(Ln / 32, CGn / 32, Bn), dim3(32, 8)>>>();
    attn_fused<<<dim3(Ln / 64, Bn), 256, AT_SMEM>>>();
    final_mma<<<dim3(Cn / 128, Ln / 128, Bn), 256, F_SMEM>>>(x, Wo, bo, gamma, out);
}